// round 15
// baseline (speedup 1.0000x reference)
#include <cuda_runtime.h>
#include <cuda_fp16.h>
#include <cstdint>

// Problem constants
#define Bb   2
#define Ss   2048
#define Dd   4096
#define Hh   32
#define HDd  128
#define ALl  10
#define Mrows (Bb * Ss)   // 4096
#define Ncat (3 * Dd)

__device__ __forceinline__ uint32_t smem_u32(const void* p) {
    uint32_t a;
    asm("{ .reg .u64 t; cvta.to.shared.u64 t, %1; cvt.u32.u64 %0, t; }" : "=r"(a) : "l"(p));
    return a;
}
__device__ __forceinline__ void cp16(void* smem_dst, const void* gsrc) {
    uint32_t s = smem_u32(smem_dst);
    asm volatile("cp.async.cg.shared.global [%0], [%1], 16;" :: "r"(s), "l"(gsrc));
}
#define CP_COMMIT() asm volatile("cp.async.commit_group;" ::: "memory")
#define CP_WAIT(n)  asm volatile("cp.async.wait_group %0;" :: "n"(n) : "memory")

// fp16 m16n8k16 mma, fp32 accum
__device__ __forceinline__ void mma16816(float* c, const uint32_t* a, const uint32_t* b) {
    asm volatile(
        "mma.sync.aligned.m16n8k16.row.col.f32.f16.f16.f32 "
        "{%0,%1,%2,%3}, {%4,%5,%6,%7}, {%8,%9}, {%0,%1,%2,%3};"
        : "+f"(c[0]), "+f"(c[1]), "+f"(c[2]), "+f"(c[3])
        : "r"(a[0]), "r"(a[1]), "r"(a[2]), "r"(a[3]), "r"(b[0]), "r"(b[1]));
}

// ---------------------------------------------------------------------------
// Scratch buffers
// ---------------------------------------------------------------------------
__device__ float g_q32[Mrows * Dd];
__device__ float g_k32[Mrows * Dd];
__device__ float g_xv [Mrows * Dd];
__device__ float g_ak[ALl * Dd];
__device__ float g_av[ALl * Dd];
__device__ float g_ap[(size_t)Bb * Hh * Ss * 12];   // gated adapter probs

__device__ __half g_xhi[Mrows * Dd];   // x split (A-side), later O split
__device__ __half g_xlo[Mrows * Dd];
__device__ __half g_qhi[Mrows * Dd];   // Q post-rope split (A-side in QK^T)
__device__ __half g_qlo[Mrows * Dd];
__device__ __half g_ks [Mrows * Dd];   // K post-rope single (B-side)
__device__ __half g_vts[Mrows * Dd];   // V^T per head [b,h,d,s] single (B-side)
// concatenated transposed weights fp16: rows [0,4096)=Wq^T, [4096,8192)=Wk^T,
// [8192,12288)=Wv^T
__device__ __half g_wcat[(size_t)Ncat * Dd];
__device__ __half g_wo[Dd * Dd];

// ---------------------------------------------------------------------------
// Split fp32 -> fp16 hi + fp16 lo (A-side operands: exact 2-term)
// ---------------------------------------------------------------------------
__global__ __launch_bounds__(256) void split_kernel(
    const float* __restrict__ A, __half* __restrict__ hi,
    __half* __restrict__ lo)
{
    const int i = blockIdx.x * 256 + threadIdx.x;
    float4 v = ((const float4*)A)[i];
    float vv[4] = {v.x, v.y, v.z, v.w};
    __half h[4], l[4];
    #pragma unroll
    for (int j = 0; j < 4; j++) {
        h[j] = __float2half(vv[j]);
        l[j] = __float2half(vv[j] - __half2float(h[j]));
    }
    ((__half2*)hi)[2 * i]     = __halves2half2(h[0], h[1]);
    ((__half2*)hi)[2 * i + 1] = __halves2half2(h[2], h[3]);
    ((__half2*)lo)[2 * i]     = __halves2half2(l[0], l[1]);
    ((__half2*)lo)[2 * i + 1] = __halves2half2(l[2], l[3]);
}

// ---------------------------------------------------------------------------
// RoPE + split for Q (hi/lo) and K (single): reads fp32 GEMM outputs
// ---------------------------------------------------------------------------
__global__ __launch_bounds__(256) void ropesplit_kernel(
    const float* __restrict__ q32, const float* __restrict__ k32,
    __half* __restrict__ qhi, __half* __restrict__ qlo,
    __half* __restrict__ ks,
    const float* __restrict__ cosb, const float* __restrict__ sinb)
{
    const int idx = blockIdx.x * 256 + threadIdx.x;   // pair id
    const int j = idx & 63;
    const int h = (idx >> 6) & 31;
    const int s = (idx >> 11) & (Ss - 1);
    const size_t base = ((size_t)(idx >> 11)) * Dd + h * HDd + 2 * j;
    const float c  = cosb[s * 64 + j];
    const float sn = sinb[s * 64 + j];

    float q0 = q32[base], q1 = q32[base + 1];
    float o0 = q0 * c - q1 * sn, o1 = q0 * sn + q1 * c;
    __half h0 = __float2half(o0), h1 = __float2half(o1);
    *(__half2*)(qhi + base) = __halves2half2(h0, h1);
    *(__half2*)(qlo + base) = __halves2half2(
        __float2half(o0 - __half2float(h0)),
        __float2half(o1 - __half2float(h1)));

    float k0 = k32[base], k1 = k32[base + 1];
    float ko0 = k0 * c - k1 * sn, ko1 = k0 * sn + k1 * c;
    *(__half2*)(ks + base) = __halves2half2(__float2half(ko0), __float2half(ko1));
}

// ---------------------------------------------------------------------------
// Transpose: W[K,N] fp32 -> Wt[N,K] fp16 single (writes at offset pointer)
// ---------------------------------------------------------------------------
__global__ __launch_bounds__(256) void tsplit_kernel(
    const float* __restrict__ W, __half* __restrict__ o)
{
    __shared__ float t[32][33];
    const int tx = threadIdx.x, ty = threadIdx.y;
    const int x = blockIdx.x * 32 + tx;
    const int y0 = blockIdx.y * 32;
    #pragma unroll
    for (int j = ty; j < 32; j += 8)
        t[j][tx] = W[(size_t)(y0 + j) * Dd + x];
    __syncthreads();
    const int ox = blockIdx.y * 32 + tx;
    const int oy0 = blockIdx.x * 32;
    #pragma unroll
    for (int j = ty; j < 32; j += 8)
        o[(size_t)(oy0 + j) * Dd + ox] = __float2half(t[tx][j]);
}

// ---------------------------------------------------------------------------
// V transpose per head: xv fp32 [(b,s),(h,d)] -> vt fp16 [(b,h,d),(s)]
// ---------------------------------------------------------------------------
__global__ __launch_bounds__(256) void vtsplit_kernel(
    const float* __restrict__ V, __half* __restrict__ o)
{
    __shared__ float t[32][33];
    const int tx = threadIdx.x, ty = threadIdx.y;
    const int bh = blockIdx.z;
    const int b = bh >> 5, h = bh & 31;
    const int s0 = blockIdx.x * 32;
    const int d0 = blockIdx.y * 32;
    #pragma unroll
    for (int j = ty; j < 32; j += 8)
        t[j][tx] = V[(size_t)(b * Ss + s0 + j) * Dd + h * HDd + d0 + tx];
    __syncthreads();
    #pragma unroll
    for (int j = ty; j < 32; j += 8)
        o[((size_t)bh * HDd + d0 + j) * Ss + s0 + tx] = __float2half(t[tx][j]);
}

// ---------------------------------------------------------------------------
// HMMA GEMM mainloop: 128x128 tile, BK=32, fp16 A-hi/lo + B-single (2-term),
// 4-stage cp.async pipeline with XOR chunk swizzle, 2 CTAs/SM.
// FUSED=1: B is [Wq|Wk|Wv] concat (N=12288); C pointer picked per CTA section.
// FUSED=0: plain C = A@B^T (output projection).
// Epilogue is uniform fp32 either way (no register-pressure divergence).
// ---------------------------------------------------------------------------
#define TILEB  8192                   // 128 rows x 64 B
#define STAGEB (3 * TILEB)            // Ah, Al, B = 24576 B
#define GSMEM  (4 * STAGEB)           // 98304 B -> 2 CTAs/SM

template<int FUSED>
__global__ __launch_bounds__(256, 2) void gemm_hmma(
    const __half* __restrict__ Ahi, const __half* __restrict__ Alo,
    const __half* __restrict__ B,
    float* __restrict__ C0, float* __restrict__ C1, float* __restrict__ C2)
{
    extern __shared__ char smem[];
    const int tid  = threadIdx.x;
    const int wid  = tid >> 5;
    const int lane = tid & 31;
    const int gid  = lane >> 2;
    const int tq   = lane & 3;

    const int warp_m = (wid & 3) * 32;
    const int warp_n = (wid >> 2) * 64;
    const size_t arow0 = (size_t)blockIdx.y * 128;
    const size_t brow0 = (size_t)blockIdx.x * 128;

    // Per-CTA destination (uniform): section of the concatenated N range
    float* Cd;
    size_t ccol0;
    if (FUSED) {
        const int sec = (int)(brow0 >> 12);
        Cd = (sec == 0) ? C0 : (sec == 1) ? C1 : C2;
        ccol0 = brow0 & 4095;
    } else {
        Cd = C0;
        ccol0 = brow0;
    }

    const uint32_t swv = (uint32_t)((gid & 6) >> 1);
    uint32_t co[4];
    #pragma unroll
    for (int c = 0; c < 4; c++) co[c] = ((uint32_t)c ^ swv) << 4;
    const uint32_t tqb = (uint32_t)(tq * 4);

    float acc[2][8][4];
    #pragma unroll
    for (int mt = 0; mt < 2; mt++)
        #pragma unroll
        for (int nt = 0; nt < 8; nt++)
            #pragma unroll
            for (int j = 0; j < 4; j++) acc[mt][nt][j] = 0.0f;

    auto load_stage = [&](int s, int k0) {
        char* stg = smem + s * STAGEB;
        #pragma unroll
        for (int i = tid; i < 512; i += 256) {
            const int r = i >> 2, kc = i & 3;
            const int kcs = kc ^ ((r & 6) >> 1);
            const size_t ga = (arow0 + r) * (size_t)Dd + k0 + kc * 8;
            const size_t gb = (brow0 + r) * (size_t)Dd + k0 + kc * 8;
            char* dst = stg + r * 64 + kcs * 16;
            cp16(dst,             Ahi + ga);
            cp16(dst + TILEB,     Alo + ga);
            cp16(dst + 2 * TILEB, B + gb);
        }
        CP_COMMIT();
    };

    const int NCH = Dd / 32;   // 128
    load_stage(0, 0);
    load_stage(1, 32);
    load_stage(2, 64);
    CP_WAIT(2);
    __syncthreads();

    for (int ch = 0; ch < NCH; ch++) {
        if (ch + 3 < NCH) load_stage((ch + 3) & 3, (ch + 3) * 32);

        const char* stg = smem + (ch & 3) * STAGEB;
        const char* sAh = stg;
        const char* sAl = stg + TILEB;
        const char* sB  = stg + 2 * TILEB;

        #pragma unroll
        for (int ks = 0; ks < 2; ks++) {
            const uint32_t c0 = co[ks * 2], c1 = co[ks * 2 + 1];
            uint32_t ah[2][4], al[2][4];
            #pragma unroll
            for (int mt = 0; mt < 2; mt++) {
                const uint32_t r0b = (uint32_t)((warp_m + mt * 16 + gid) * 64) + tqb;
                const uint32_t r1b = r0b + 8 * 64;
                ah[mt][0] = *(const uint32_t*)(sAh + r0b + c0);
                ah[mt][1] = *(const uint32_t*)(sAh + r1b + c0);
                ah[mt][2] = *(const uint32_t*)(sAh + r0b + c1);
                ah[mt][3] = *(const uint32_t*)(sAh + r1b + c1);
                al[mt][0] = *(const uint32_t*)(sAl + r0b + c0);
                al[mt][1] = *(const uint32_t*)(sAl + r1b + c0);
                al[mt][2] = *(const uint32_t*)(sAl + r0b + c1);
                al[mt][3] = *(const uint32_t*)(sAl + r1b + c1);
            }
            #pragma unroll
            for (int nt = 0; nt < 8; nt++) {
                const uint32_t nb = (uint32_t)((warp_n + nt * 8 + gid) * 64) + tqb;
                uint32_t bf[2];
                bf[0] = *(const uint32_t*)(sB + nb + c0);
                bf[1] = *(const uint32_t*)(sB + nb + c1);
                #pragma unroll
                for (int mt = 0; mt < 2; mt++) {
                    mma16816(acc[mt][nt], ah[mt], bf);
                    mma16816(acc[mt][nt], al[mt], bf);
                }
            }
        }

        if (ch < NCH - 3)       CP_WAIT(2);
        else if (ch == NCH - 3) CP_WAIT(1);
        else                    CP_WAIT(0);
        __syncthreads();
    }

    #pragma unroll
    for (int mt = 0; mt < 2; mt++) {
        const size_t r0 = arow0 + warp_m + mt * 16 + gid;
        #pragma unroll
        for (int nt = 0; nt < 8; nt++) {
            const size_t c = ccol0 + warp_n + nt * 8 + tq * 2;
            *(float2*)(Cd + r0 * Dd + c)       = make_float2(acc[mt][nt][0], acc[mt][nt][1]);
            *(float2*)(Cd + (r0 + 8) * Dd + c) = make_float2(acc[mt][nt][2], acc[mt][nt][3]);
        }
    }
}

// ---------------------------------------------------------------------------
// Adapter GEMM: C[AL, D] = A[AL, D] @ W[D, D]  (tiny M=10, fp32)
// ---------------------------------------------------------------------------
__global__ __launch_bounds__(256) void adapter_gemm(
    const float* __restrict__ A, const float* __restrict__ W,
    float* __restrict__ C)
{
    __shared__ float sA[ALl][256];
    const int n = blockIdx.x * 256 + threadIdx.x;

    float acc[ALl];
    #pragma unroll
    for (int l = 0; l < ALl; l++) acc[l] = 0.0f;

    for (int k0 = 0; k0 < Dd; k0 += 256) {
        for (int i = threadIdx.x; i < ALl * 256; i += 256)
            sA[i >> 8][i & 255] = A[(size_t)(i >> 8) * Dd + k0 + (i & 255)];
        __syncthreads();
        for (int kk = 0; kk < 256; kk++) {
            float w = W[(size_t)(k0 + kk) * Dd + n];
            #pragma unroll
            for (int l = 0; l < ALl; l++)
                acc[l] = fmaf(sA[l][kk], w, acc[l]);
        }
        __syncthreads();
    }
    #pragma unroll
    for (int l = 0; l < ALl; l++) C[(size_t)l * Dd + n] = acc[l];
}

// ---------------------------------------------------------------------------
// Adapter probs: ap[bh][s][l] = gate[h] * softmax_l(Q[s,h,:]·AK[l,h,:]*scale)
// ---------------------------------------------------------------------------
__global__ __launch_bounds__(128) void adapter_probs(
    const __half* __restrict__ qhi, const __half* __restrict__ qlo,
    const float* __restrict__ akw, const float* __restrict__ gate,
    float* __restrict__ ap)
{
    __shared__ float sak[ALl][128];
    const int tid = threadIdx.x;
    const int bh = blockIdx.y;
    const int b = bh >> 5, h = bh & 31;
    const int s = blockIdx.x * 128 + tid;
    const float scale = 0.08838834764831845f;

    for (int i = tid; i < ALl * 128; i += 128)
        sak[i >> 7][i & 127] = akw[(size_t)(i >> 7) * Dd + h * HDd + (i & 127)];
    __syncthreads();

    const size_t qb = (size_t)(b * Ss + s) * Dd + h * HDd;
    float acc[ALl];
    #pragma unroll
    for (int l = 0; l < ALl; l++) acc[l] = 0.0f;
    #pragma unroll 4
    for (int c = 0; c < 16; c++) {
        uint4 vh = *(const uint4*)(qhi + qb + c * 8);
        uint4 vl = *(const uint4*)(qlo + qb + c * 8);
        const __half2* ph = (const __half2*)&vh;
        const __half2* pl = (const __half2*)&vl;
        #pragma unroll
        for (int u = 0; u < 4; u++) {
            float q0 = __low2float(ph[u])  + __low2float(pl[u]);
            float q1 = __high2float(ph[u]) + __high2float(pl[u]);
            const int d = c * 8 + u * 2;
            #pragma unroll
            for (int l = 0; l < ALl; l++)
                acc[l] = fmaf(q0, sak[l][d], fmaf(q1, sak[l][d + 1], acc[l]));
        }
    }
    float amax = -1e30f;
    #pragma unroll
    for (int l = 0; l < ALl; l++) { acc[l] *= scale; amax = fmaxf(amax, acc[l]); }
    float asum = 0.0f;
    #pragma unroll
    for (int l = 0; l < ALl; l++) { acc[l] = __expf(acc[l] - amax); asum += acc[l]; }
    const float g = gate[h] / asum;
    float* dst = ap + ((size_t)bh * Ss + s) * 12;
    #pragma unroll
    for (int l = 0; l < ALl; l++) dst[l] = acc[l] * g;
}

// ---------------------------------------------------------------------------
// FA2-style tensor-core attention, fp16 2-term: Q/P hi/lo (A-side exact),
// K/V^T single (B-side). 128 queries/CTA, 8 warps x 16 rows, K tiles of 64.
// ---------------------------------------------------------------------------
#define QSTR 136
#define VSTR 72
#define A_OFF_Q  0                       // Qh 34816 + Ql 34816
#define A_OFF_K  69632                   // K single stage 17408 x2
#define A_OFF_V  104448                  // V single stage 18432 x2
#define A_OFF_AV 141312                  // fp32 10x132 = 5280
#define ATTN2_SMEM 146592

__global__ __launch_bounds__(256, 1) void attn_tc2(
    const __half* __restrict__ qhi, const __half* __restrict__ qlo,
    const __half* __restrict__ ks,  const __half* __restrict__ vts,
    const float* __restrict__ ap, const float* __restrict__ avw,
    __half* __restrict__ ohi, __half* __restrict__ olo)
{
    extern __shared__ char sm[];
    __half* sQh = (__half*)(sm + A_OFF_Q);
    __half* sQl = sQh + 128 * QSTR;
    float* sAV = (float*)(sm + A_OFF_AV);

    const int tid  = threadIdx.x;
    const int wid  = tid >> 5;
    const int lane = tid & 31;
    const int gid  = lane >> 2;
    const int tq   = lane & 3;

    const int qt = (gridDim.x - 1) - blockIdx.x;
    const int bh = blockIdx.y;
    const int b  = bh >> 5;
    const int h  = bh & 31;
    const float scale = 0.08838834764831845f;

    const int wm = wid * 16;
    const size_t qgbase = ((size_t)(b * Ss) + qt * 128) * Dd + h * HDd;
    const size_t vgbase = (size_t)bh * HDd * Ss;

    for (int i = tid; i < 2048; i += 256) {
        const int r = i >> 4, c = i & 15;
        *(uint4*)(sQh + r * QSTR + c * 8) = *(const uint4*)(qhi + qgbase + (size_t)r * Dd + c * 8);
        *(uint4*)(sQl + r * QSTR + c * 8) = *(const uint4*)(qlo + qgbase + (size_t)r * Dd + c * 8);
    }
    for (int i = tid; i < ALl * HDd; i += 256) {
        const int l = i >> 7, d = i & 127;
        sAV[l * 132 + d] = avw[(size_t)l * Dd + h * HDd + d];
    }

    auto prefetch = [&](int kt_, int s) {
        __half* kh = (__half*)(sm + A_OFF_K + s * 17408);
        __half* vh = (__half*)(sm + A_OFF_V + s * 18432);
        const size_t kb = ((size_t)(b * Ss) + kt_ * 64) * Dd + h * HDd;
        const size_t vb = vgbase + (size_t)kt_ * 64;
        for (int i = tid; i < 1024; i += 256) {
            const int r = i >> 4, c = i & 15;
            cp16(kh + r * QSTR + c * 8, ks + kb + (size_t)r * Dd + c * 8);
        }
        for (int i = tid; i < 1024; i += 256) {
            const int d = i >> 3, c = i & 7;
            cp16(vh + d * VSTR + c * 8, vts + vb + (size_t)d * Ss + c * 8);
        }
        CP_COMMIT();
    };

    prefetch(0, 0);

    const int rq0 = qt * 128 + wm + gid;
    const int rq1 = rq0 + 8;

    float m0 = -1e30f, m1 = -1e30f, l0 = 0.0f, l1 = 0.0f;
    float o[16][4];
    #pragma unroll
    for (int nt = 0; nt < 16; nt++)
        #pragma unroll
        for (int j = 0; j < 4; j++) o[nt][j] = 0.0f;

    const int ktmax = 2 * qt + 1;
    for (int kt = 0; kt <= ktmax; kt++) {
        const int s = kt & 1;
        if (kt < ktmax) { prefetch(kt + 1, s ^ 1); CP_WAIT(1); }
        else            { CP_WAIT(0); }
        __syncthreads();

        const __half* kh = (const __half*)(sm + A_OFF_K + s * 17408);

        float sacc[8][4];
        #pragma unroll
        for (int nt = 0; nt < 8; nt++)
            #pragma unroll
            for (int j = 0; j < 4; j++) sacc[nt][j] = 0.0f;

        #pragma unroll
        for (int ksx = 0; ksx < 8; ksx++) {
            const int kb = ksx * 16 + tq * 2;
            const int ra = wm + gid;
            uint32_t ah[4], al[4];
            ah[0] = *(const uint32_t*)(sQh + ra * QSTR + kb);
            ah[1] = *(const uint32_t*)(sQh + (ra + 8) * QSTR + kb);
            ah[2] = *(const uint32_t*)(sQh + ra * QSTR + kb + 8);
            ah[3] = *(const uint32_t*)(sQh + (ra + 8) * QSTR + kb + 8);
            al[0] = *(const uint32_t*)(sQl + ra * QSTR + kb);
            al[1] = *(const uint32_t*)(sQl + (ra + 8) * QSTR + kb);
            al[2] = *(const uint32_t*)(sQl + ra * QSTR + kb + 8);
            al[3] = *(const uint32_t*)(sQl + (ra + 8) * QSTR + kb + 8);
            #pragma unroll
            for (int nt = 0; nt < 8; nt++) {
                const int n = nt * 8 + gid;
                uint32_t bf[2];
                bf[0] = *(const uint32_t*)(kh + n * QSTR + kb);
                bf[1] = *(const uint32_t*)(kh + n * QSTR + kb + 8);
                mma16816(sacc[nt], ah, bf);
                mma16816(sacc[nt], al, bf);
            }
        }

        const bool maybe = (kt >= 2 * qt);
        #pragma unroll
        for (int nt = 0; nt < 8; nt++) {
            const int c = kt * 64 + nt * 8 + tq * 2;
            sacc[nt][0] *= scale; sacc[nt][1] *= scale;
            sacc[nt][2] *= scale; sacc[nt][3] *= scale;
            if (maybe) {
                if (c     > rq0) sacc[nt][0] = -1e30f;
                if (c + 1 > rq0) sacc[nt][1] = -1e30f;
                if (c     > rq1) sacc[nt][2] = -1e30f;
                if (c + 1 > rq1) sacc[nt][3] = -1e30f;
            }
        }

        float mx0 = -1e30f, mx1 = -1e30f;
        #pragma unroll
        for (int nt = 0; nt < 8; nt++) {
            mx0 = fmaxf(mx0, fmaxf(sacc[nt][0], sacc[nt][1]));
            mx1 = fmaxf(mx1, fmaxf(sacc[nt][2], sacc[nt][3]));
        }
        mx0 = fmaxf(mx0, __shfl_xor_sync(0xFFFFFFFFu, mx0, 1));
        mx0 = fmaxf(mx0, __shfl_xor_sync(0xFFFFFFFFu, mx0, 2));
        mx1 = fmaxf(mx1, __shfl_xor_sync(0xFFFFFFFFu, mx1, 1));
        mx1 = fmaxf(mx1, __shfl_xor_sync(0xFFFFFFFFu, mx1, 2));
        const float mn0 = fmaxf(m0, mx0), mn1 = fmaxf(m1, mx1);
        const float a0 = __expf(m0 - mn0), a1 = __expf(m1 - mn1);
        m0 = mn0; m1 = mn1;

        float sum0 = 0.0f, sum1 = 0.0f;
        #pragma unroll
        for (int nt = 0; nt < 8; nt++) {
            sacc[nt][0] = __expf(sacc[nt][0] - m0);
            sacc[nt][1] = __expf(sacc[nt][1] - m0);
            sacc[nt][2] = __expf(sacc[nt][2] - m1);
            sacc[nt][3] = __expf(sacc[nt][3] - m1);
            sum0 += sacc[nt][0] + sacc[nt][1];
            sum1 += sacc[nt][2] + sacc[nt][3];
        }
        sum0 += __shfl_xor_sync(0xFFFFFFFFu, sum0, 1);
        sum0 += __shfl_xor_sync(0xFFFFFFFFu, sum0, 2);
        sum1 += __shfl_xor_sync(0xFFFFFFFFu, sum1, 1);
        sum1 += __shfl_xor_sync(0xFFFFFFFFu, sum1, 2);
        l0 = l0 * a0 + sum0;
        l1 = l1 * a1 + sum1;

        #pragma unroll
        for (int nt = 0; nt < 16; nt++) {
            o[nt][0] *= a0; o[nt][1] *= a0;
            o[nt][2] *= a1; o[nt][3] *= a1;
        }

        // P -> fp16 hi/lo A-fragments (exact 2-term)
        uint32_t pfh[4][4], pfl[4][4];
        #pragma unroll
        for (int kc = 0; kc < 4; kc++) {
            #pragma unroll
            for (int half_ = 0; half_ < 2; half_++) {
                const int nt = 2 * kc + half_;
                float p0 = sacc[nt][0], p1 = sacc[nt][1];
                float p2 = sacc[nt][2], p3 = sacc[nt][3];
                __half h0 = __float2half(p0), h1 = __float2half(p1);
                __half h2 = __float2half(p2), h3 = __float2half(p3);
                __half2 hv01 = __halves2half2(h0, h1), hv23 = __halves2half2(h2, h3);
                pfh[kc][half_ * 2]     = *(uint32_t*)&hv01;
                pfh[kc][half_ * 2 + 1] = *(uint32_t*)&hv23;
                __half2 lv01 = __halves2half2(__float2half(p0 - __half2float(h0)),
                                              __float2half(p1 - __half2float(h1)));
                __half2 lv23 = __halves2half2(__float2half(p2 - __half2float(h2)),
                                              __float2half(p3 - __half2float(h3)));
                pfl[kc][half_ * 2]     = *(uint32_t*)&lv01;
                pfl[kc][half_ * 2 + 1] = *(uint32_t*)&lv23;
            }
        }

        const __half* vh = (const __half*)(sm + A_OFF_V + s * 18432);
        #pragma unroll
        for (int kc = 0; kc < 4; kc++) {
            const int kb = kc * 16 + tq * 2;
            #pragma unroll
            for (int nt = 0; nt < 16; nt++) {
                const int n = nt * 8 + gid;
                uint32_t vf[2];
                vf[0] = *(const uint32_t*)(vh + n * VSTR + kb);
                vf[1] = *(const uint32_t*)(vh + n * VSTR + kb + 8);
                mma16816(o[nt], pfh[kc], vf);
                mma16816(o[nt], pfl[kc], vf);
            }
        }
        __syncthreads();
    }

    const float li0 = 1.0f / l0, li1 = 1.0f / l1;
    const float* ap0p = ap + ((size_t)bh * Ss + rq0) * 12;
    const float* ap1p = ap + ((size_t)bh * Ss + rq1) * 12;
    float ap0[ALl], ap1[ALl];
    #pragma unroll
    for (int l = 0; l < ALl; l++) { ap0[l] = ap0p[l]; ap1[l] = ap1p[l]; }

    const size_t ob0 = qgbase + (size_t)(wm + gid) * Dd;
    const size_t ob1 = ob0 + 8 * Dd;
    #pragma unroll
    for (int nt = 0; nt < 16; nt++) {
        const int c = nt * 8 + tq * 2;
        float v0 = o[nt][0] * li0, v1 = o[nt][1] * li0;
        float v2 = o[nt][2] * li1, v3 = o[nt][3] * li1;
        #pragma unroll
        for (int l = 0; l < ALl; l++) {
            const float av0 = sAV[l * 132 + c];
            const float av1 = sAV[l * 132 + c + 1];
            v0 = fmaf(ap0[l], av0, v0);
            v1 = fmaf(ap0[l], av1, v1);
            v2 = fmaf(ap1[l], av0, v2);
            v3 = fmaf(ap1[l], av1, v3);
        }
        __half h0 = __float2half(v0), h1 = __float2half(v1);
        __half h2 = __float2half(v2), h3 = __float2half(v3);
        *(__half2*)(ohi + ob0 + c) = __halves2half2(h0, h1);
        *(__half2*)(ohi + ob1 + c) = __halves2half2(h2, h3);
        *(__half2*)(olo + ob0 + c) = __halves2half2(
            __float2half(v0 - __half2float(h0)),
            __float2half(v1 - __half2float(h1)));
        *(__half2*)(olo + ob1 + c) = __halves2half2(
            __float2half(v2 - __half2float(h2)),
            __float2half(v3 - __half2float(h3)));
    }
}

// ---------------------------------------------------------------------------
// Launch
// Inputs: 0=x 1=cos 2=sin 3=mask(unused) 4=wq 5=wk 6=wv 7=wo 8=gate 9=adapter
// ---------------------------------------------------------------------------
extern "C" void kernel_launch(void* const* d_in, const int* in_sizes, int n_in,
                              void* d_out, int out_size)
{
    const float* x       = (const float*)d_in[0];
    const float* cosb    = (const float*)d_in[1];
    const float* sinb    = (const float*)d_in[2];
    const float* wq      = (const float*)d_in[4];
    const float* wk      = (const float*)d_in[5];
    const float* wv      = (const float*)d_in[6];
    const float* wo      = (const float*)d_in[7];
    const float* gate    = (const float*)d_in[8];
    const float* adapter = (const float*)d_in[9];
    float* out = (float*)d_out;

    float *q32, *k32, *xv, *akp, *avp, *app;
    cudaGetSymbolAddress((void**)&q32, g_q32);
    cudaGetSymbolAddress((void**)&k32, g_k32);
    cudaGetSymbolAddress((void**)&xv,  g_xv);
    cudaGetSymbolAddress((void**)&akp, g_ak);
    cudaGetSymbolAddress((void**)&avp, g_av);
    cudaGetSymbolAddress((void**)&app, g_ap);

    __half *xhi, *xlo, *qhi, *qlo, *ksb, *vtb, *wcat, *woh;
    cudaGetSymbolAddress((void**)&xhi,  g_xhi);
    cudaGetSymbolAddress((void**)&xlo,  g_xlo);
    cudaGetSymbolAddress((void**)&qhi,  g_qhi);
    cudaGetSymbolAddress((void**)&qlo,  g_qlo);
    cudaGetSymbolAddress((void**)&ksb,  g_ks);
    cudaGetSymbolAddress((void**)&vtb,  g_vts);
    cudaGetSymbolAddress((void**)&wcat, g_wcat);
    cudaGetSymbolAddress((void**)&woh,  g_wo);

    cudaFuncSetAttribute(gemm_hmma<1>, cudaFuncAttributeMaxDynamicSharedMemorySize, GSMEM);
    cudaFuncSetAttribute(gemm_hmma<0>, cudaFuncAttributeMaxDynamicSharedMemorySize, GSMEM);
    cudaFuncSetAttribute(attn_tc2, cudaFuncAttributeMaxDynamicSharedMemorySize, ATTN2_SMEM);

    // Weight transpose (fp16) into concatenated buffer sections + Wo
    dim3 tb(32, 8), tg(Dd / 32, Dd / 32);
    tsplit_kernel<<<tg, tb>>>(wq, wcat);
    tsplit_kernel<<<tg, tb>>>(wk, wcat + (size_t)Dd * Dd);
    tsplit_kernel<<<tg, tb>>>(wv, wcat + (size_t)2 * Dd * Dd);
    tsplit_kernel<<<tg, tb>>>(wo, woh);

    // x split (fp16 hi/lo)
    split_kernel<<<(Mrows * Dd / 4) / 256, 256>>>(x, xhi, xlo);

    // Fused QKV projection: one GEMM, fp32 outputs per section
    gemm_hmma<1><<<dim3(Ncat / 128, Mrows / 128), 256, GSMEM>>>(
        xhi, xlo, wcat, q32, k32, xv);

    // RoPE + fp16 conversion for Q (hi/lo) and K (single)
    ropesplit_kernel<<<(Mrows * Dd / 2) / 256, 256>>>(
        q32, k32, qhi, qlo, ksb, cosb, sinb);

    vtsplit_kernel<<<dim3(Ss / 32, HDd / 32, Bb * Hh), tb>>>(xv, vtb);

    adapter_gemm<<<Dd / 256, 256>>>(adapter, wk, akp);
    adapter_gemm<<<Dd / 256, 256>>>(adapter, wv, avp);
    adapter_probs<<<dim3(Ss / 128, Bb * Hh), 128>>>(qhi, qlo, akp, gate, app);

    // FA2 tensor-core attention -> O hi/lo (reuse x split buffers)
    attn_tc2<<<dim3(Ss / 128, Bb * Hh), 256, ATTN2_SMEM>>>(
        qhi, qlo, ksb, vtb, app, avp, xhi, xlo);

    // Output projection
    gemm_hmma<0><<<dim3(Dd / 128, Mrows / 128), 256, GSMEM>>>(
        xhi, xlo, woh, out, nullptr, nullptr);
}

// round 16
// speedup vs baseline: 1.3239x; 1.3239x over previous
#include <cuda_runtime.h>
#include <cuda_fp16.h>
#include <cstdint>

// Problem constants
#define Bb   2
#define Ss   2048
#define Dd   4096
#define Hh   32
#define HDd  128
#define ALl  10
#define Mrows (Bb * Ss)   // 4096

__device__ __forceinline__ uint32_t smem_u32(const void* p) {
    uint32_t a;
    asm("{ .reg .u64 t; cvta.to.shared.u64 t, %1; cvt.u32.u64 %0, t; }" : "=r"(a) : "l"(p));
    return a;
}
__device__ __forceinline__ void cp16(void* smem_dst, const void* gsrc) {
    uint32_t s = smem_u32(smem_dst);
    asm volatile("cp.async.cg.shared.global [%0], [%1], 16;" :: "r"(s), "l"(gsrc));
}
#define CP_COMMIT() asm volatile("cp.async.commit_group;" ::: "memory")
#define CP_WAIT(n)  asm volatile("cp.async.wait_group %0;" :: "n"(n) : "memory")

// fp16 m16n8k16 mma, fp32 accum
__device__ __forceinline__ void mma16816(float* c, const uint32_t* a, const uint32_t* b) {
    asm volatile(
        "mma.sync.aligned.m16n8k16.row.col.f32.f16.f16.f32 "
        "{%0,%1,%2,%3}, {%4,%5,%6,%7}, {%8,%9}, {%0,%1,%2,%3};"
        : "+f"(c[0]), "+f"(c[1]), "+f"(c[2]), "+f"(c[3])
        : "r"(a[0]), "r"(a[1]), "r"(a[2]), "r"(a[3]), "r"(b[0]), "r"(b[1]));
}

// ---------------------------------------------------------------------------
// Scratch buffers
// ---------------------------------------------------------------------------
__device__ float g_xv[Mrows * Dd];
__device__ float g_ak[ALl * Dd];
__device__ float g_av[ALl * Dd];
__device__ float g_ap[(size_t)Bb * Hh * Ss * 12];   // gated adapter probs

__device__ __half g_xh [Mrows * Dd];   // x fp16 single; later O fp16 single
__device__ __half g_qhi[Mrows * Dd];   // Q post-rope split (A-side in QK^T)
__device__ __half g_qlo[Mrows * Dd];
__device__ __half g_ks [Mrows * Dd];   // K post-rope single (B-side)
__device__ __half g_vts[Mrows * Dd];   // V^T per head [b,h,d,s] single (B-side)
// transposed weights, single fp16: Wt[n][k] = W[k][n]
__device__ __half g_wq[Dd * Dd];
__device__ __half g_wk[Dd * Dd];
__device__ __half g_wv[Dd * Dd];
__device__ __half g_wo[Dd * Dd];

// ---------------------------------------------------------------------------
// Convert fp32 -> fp16 single
// ---------------------------------------------------------------------------
__global__ __launch_bounds__(256) void tofp16_kernel(
    const float* __restrict__ A, __half* __restrict__ o)
{
    const int i = blockIdx.x * 256 + threadIdx.x;
    float4 v = ((const float4*)A)[i];
    ((__half2*)o)[2 * i]     = __halves2half2(__float2half(v.x), __float2half(v.y));
    ((__half2*)o)[2 * i + 1] = __halves2half2(__float2half(v.z), __float2half(v.w));
}

// ---------------------------------------------------------------------------
// Transpose: W[K,N] fp32 -> Wt[N,K] fp16 single
// ---------------------------------------------------------------------------
__global__ __launch_bounds__(256) void tsplit_kernel(
    const float* __restrict__ W, __half* __restrict__ o)
{
    __shared__ float t[32][33];
    const int tx = threadIdx.x, ty = threadIdx.y;
    const int x = blockIdx.x * 32 + tx;
    const int y0 = blockIdx.y * 32;
    #pragma unroll
    for (int j = ty; j < 32; j += 8)
        t[j][tx] = W[(size_t)(y0 + j) * Dd + x];
    __syncthreads();
    const int ox = blockIdx.y * 32 + tx;
    const int oy0 = blockIdx.x * 32;
    #pragma unroll
    for (int j = ty; j < 32; j += 8)
        o[(size_t)(oy0 + j) * Dd + ox] = __float2half(t[tx][j]);
}

// ---------------------------------------------------------------------------
// V transpose per head: xv fp32 [(b,s),(h,d)] -> vt fp16 [(b,h,d),(s)]
// ---------------------------------------------------------------------------
__global__ __launch_bounds__(256) void vtsplit_kernel(
    const float* __restrict__ V, __half* __restrict__ o)
{
    __shared__ float t[32][33];
    const int tx = threadIdx.x, ty = threadIdx.y;
    const int bh = blockIdx.z;
    const int b = bh >> 5, h = bh & 31;
    const int s0 = blockIdx.x * 32;
    const int d0 = blockIdx.y * 32;
    #pragma unroll
    for (int j = ty; j < 32; j += 8)
        t[j][tx] = V[(size_t)(b * Ss + s0 + j) * Dd + h * HDd + d0 + tx];
    __syncthreads();
    #pragma unroll
    for (int j = ty; j < 32; j += 8)
        o[((size_t)bh * HDd + d0 + j) * Ss + s0 + tx] = __float2half(t[tx][j]);
}

// ---------------------------------------------------------------------------
// HMMA GEMM: 128x128 tile, BK=32, single fp16 A and B (one mma per tile-op),
// 4-stage cp.async pipeline with XOR chunk swizzle, 2 CTAs/SM.
// MODE 0: fp32 C. MODE 1: RoPE + fp16 hi/lo C (Q). MODE 2: RoPE + fp16 single C (K).
// ---------------------------------------------------------------------------
#define TILEB  8192                   // 128 rows x 64 B
#define STAGEB (2 * TILEB)            // A, B = 16384 B
#define GSMEM  (4 * STAGEB)           // 65536 B -> 2 CTAs/SM

template<int MODE>
__global__ __launch_bounds__(256, 2) void gemm_hmma(
    const __half* __restrict__ A, const __half* __restrict__ B,
    float* __restrict__ C, __half* __restrict__ Chi, __half* __restrict__ Clo,
    const float* __restrict__ cosb, const float* __restrict__ sinb)
{
    extern __shared__ char smem[];
    const int tid  = threadIdx.x;
    const int wid  = tid >> 5;
    const int lane = tid & 31;
    const int gid  = lane >> 2;
    const int tq   = lane & 3;

    const int warp_m = (wid & 3) * 32;
    const int warp_n = (wid >> 2) * 64;
    const size_t arow0 = (size_t)blockIdx.y * 128;
    const size_t brow0 = (size_t)blockIdx.x * 128;

    const uint32_t swv = (uint32_t)((gid & 6) >> 1);
    uint32_t co[4];
    #pragma unroll
    for (int c = 0; c < 4; c++) co[c] = ((uint32_t)c ^ swv) << 4;
    const uint32_t tqb = (uint32_t)(tq * 4);

    float acc[2][8][4];
    #pragma unroll
    for (int mt = 0; mt < 2; mt++)
        #pragma unroll
        for (int nt = 0; nt < 8; nt++)
            #pragma unroll
            for (int j = 0; j < 4; j++) acc[mt][nt][j] = 0.0f;

    auto load_stage = [&](int s, int k0) {
        char* stg = smem + s * STAGEB;
        #pragma unroll
        for (int i = tid; i < 512; i += 256) {
            const int r = i >> 2, kc = i & 3;
            const int kcs = kc ^ ((r & 6) >> 1);
            const size_t ga = (arow0 + r) * (size_t)Dd + k0 + kc * 8;
            const size_t gb = (brow0 + r) * (size_t)Dd + k0 + kc * 8;
            char* dst = stg + r * 64 + kcs * 16;
            cp16(dst,         A + ga);
            cp16(dst + TILEB, B + gb);
        }
        CP_COMMIT();
    };

    const int NCH = Dd / 32;   // 128
    load_stage(0, 0);
    load_stage(1, 32);
    load_stage(2, 64);
    CP_WAIT(2);
    __syncthreads();

    for (int ch = 0; ch < NCH; ch++) {
        if (ch + 3 < NCH) load_stage((ch + 3) & 3, (ch + 3) * 32);

        const char* stg = smem + (ch & 3) * STAGEB;
        const char* sA = stg;
        const char* sB = stg + TILEB;

        #pragma unroll
        for (int ks = 0; ks < 2; ks++) {
            const uint32_t c0 = co[ks * 2], c1 = co[ks * 2 + 1];
            uint32_t af[2][4];
            #pragma unroll
            for (int mt = 0; mt < 2; mt++) {
                const uint32_t r0b = (uint32_t)((warp_m + mt * 16 + gid) * 64) + tqb;
                const uint32_t r1b = r0b + 8 * 64;
                af[mt][0] = *(const uint32_t*)(sA + r0b + c0);
                af[mt][1] = *(const uint32_t*)(sA + r1b + c0);
                af[mt][2] = *(const uint32_t*)(sA + r0b + c1);
                af[mt][3] = *(const uint32_t*)(sA + r1b + c1);
            }
            #pragma unroll
            for (int nt = 0; nt < 8; nt++) {
                const uint32_t nb = (uint32_t)((warp_n + nt * 8 + gid) * 64) + tqb;
                uint32_t bf[2];
                bf[0] = *(const uint32_t*)(sB + nb + c0);
                bf[1] = *(const uint32_t*)(sB + nb + c1);
                #pragma unroll
                for (int mt = 0; mt < 2; mt++)
                    mma16816(acc[mt][nt], af[mt], bf);
            }
        }

        if (ch < NCH - 3)       CP_WAIT(2);
        else if (ch == NCH - 3) CP_WAIT(1);
        else                    CP_WAIT(0);
        __syncthreads();
    }

    #pragma unroll
    for (int mt = 0; mt < 2; mt++) {
        const size_t r0 = arow0 + warp_m + mt * 16 + gid;
        #pragma unroll
        for (int nt = 0; nt < 8; nt++) {
            const size_t c = brow0 + warp_n + nt * 8 + tq * 2;
            if (MODE == 0) {
                *(float2*)(C + r0 * Dd + c)       = make_float2(acc[mt][nt][0], acc[mt][nt][1]);
                *(float2*)(C + (r0 + 8) * Dd + c) = make_float2(acc[mt][nt][2], acc[mt][nt][3]);
            } else {
                const int j = ((int)c & 127) >> 1;
                #pragma unroll
                for (int rr = 0; rr < 2; rr++) {
                    const size_t r = r0 + rr * 8;
                    const int sidx = (int)(r & (Ss - 1));
                    const float cs = cosb[sidx * 64 + j];
                    const float sn = sinb[sidx * 64 + j];
                    const float x0 = acc[mt][nt][rr * 2], x1 = acc[mt][nt][rr * 2 + 1];
                    const float o0 = x0 * cs - x1 * sn;
                    const float o1 = x0 * sn + x1 * cs;
                    __half h0 = __float2half(o0);
                    __half h1 = __float2half(o1);
                    *(__half2*)(Chi + r * Dd + c) = __halves2half2(h0, h1);
                    if (MODE == 1)
                        *(__half2*)(Clo + r * Dd + c) = __halves2half2(
                            __float2half(o0 - __half2float(h0)),
                            __float2half(o1 - __half2float(h1)));
                }
            }
        }
    }
}

// ---------------------------------------------------------------------------
// Adapter GEMM: C[AL, D] = A[AL, D] @ W[D, D]  (tiny M=10, fp32)
// ---------------------------------------------------------------------------
__global__ __launch_bounds__(256) void adapter_gemm(
    const float* __restrict__ A, const float* __restrict__ W,
    float* __restrict__ C)
{
    __shared__ float sA[ALl][256];
    const int n = blockIdx.x * 256 + threadIdx.x;

    float acc[ALl];
    #pragma unroll
    for (int l = 0; l < ALl; l++) acc[l] = 0.0f;

    for (int k0 = 0; k0 < Dd; k0 += 256) {
        for (int i = threadIdx.x; i < ALl * 256; i += 256)
            sA[i >> 8][i & 255] = A[(size_t)(i >> 8) * Dd + k0 + (i & 255)];
        __syncthreads();
        for (int kk = 0; kk < 256; kk++) {
            float w = W[(size_t)(k0 + kk) * Dd + n];
            #pragma unroll
            for (int l = 0; l < ALl; l++)
                acc[l] = fmaf(sA[l][kk], w, acc[l]);
        }
        __syncthreads();
    }
    #pragma unroll
    for (int l = 0; l < ALl; l++) C[(size_t)l * Dd + n] = acc[l];
}

// ---------------------------------------------------------------------------
// Adapter probs: ap[bh][s][l] = gate[h] * softmax_l(Q[s,h,:]·AK[l,h,:]*scale)
// ---------------------------------------------------------------------------
__global__ __launch_bounds__(128) void adapter_probs(
    const __half* __restrict__ qhi, const __half* __restrict__ qlo,
    const float* __restrict__ akw, const float* __restrict__ gate,
    float* __restrict__ ap)
{
    __shared__ float sak[ALl][128];
    const int tid = threadIdx.x;
    const int bh = blockIdx.y;
    const int b = bh >> 5, h = bh & 31;
    const int s = blockIdx.x * 128 + tid;
    const float scale = 0.08838834764831845f;

    for (int i = tid; i < ALl * 128; i += 128)
        sak[i >> 7][i & 127] = akw[(size_t)(i >> 7) * Dd + h * HDd + (i & 127)];
    __syncthreads();

    const size_t qb = (size_t)(b * Ss + s) * Dd + h * HDd;
    float acc[ALl];
    #pragma unroll
    for (int l = 0; l < ALl; l++) acc[l] = 0.0f;
    #pragma unroll 4
    for (int c = 0; c < 16; c++) {
        uint4 vh = *(const uint4*)(qhi + qb + c * 8);
        uint4 vl = *(const uint4*)(qlo + qb + c * 8);
        const __half2* ph = (const __half2*)&vh;
        const __half2* pl = (const __half2*)&vl;
        #pragma unroll
        for (int u = 0; u < 4; u++) {
            float q0 = __low2float(ph[u])  + __low2float(pl[u]);
            float q1 = __high2float(ph[u]) + __high2float(pl[u]);
            const int d = c * 8 + u * 2;
            #pragma unroll
            for (int l = 0; l < ALl; l++)
                acc[l] = fmaf(q0, sak[l][d], fmaf(q1, sak[l][d + 1], acc[l]));
        }
    }
    float amax = -1e30f;
    #pragma unroll
    for (int l = 0; l < ALl; l++) { acc[l] *= scale; amax = fmaxf(amax, acc[l]); }
    float asum = 0.0f;
    #pragma unroll
    for (int l = 0; l < ALl; l++) { acc[l] = __expf(acc[l] - amax); asum += acc[l]; }
    const float g = gate[h] / asum;
    float* dst = ap + ((size_t)bh * Ss + s) * 12;
    #pragma unroll
    for (int l = 0; l < ALl; l++) dst[l] = acc[l] * g;
}

// ---------------------------------------------------------------------------
// FA2-style tensor-core attention, fp16 2-term: Q/P hi/lo (A-side exact),
// K/V^T single (B-side). 128 queries/CTA, 8 warps x 16 rows, K tiles of 64.
// O written single fp16 (A-operand of Wo only).
// ---------------------------------------------------------------------------
#define QSTR 136
#define VSTR 72
#define A_OFF_Q  0                       // Qh 34816 + Ql 34816
#define A_OFF_K  69632                   // K single stage 17408 x2
#define A_OFF_V  104448                  // V single stage 18432 x2
#define A_OFF_AV 141312                  // fp32 10x132 = 5280
#define ATTN2_SMEM 146592

__global__ __launch_bounds__(256, 1) void attn_tc2(
    const __half* __restrict__ qhi, const __half* __restrict__ qlo,
    const __half* __restrict__ ks,  const __half* __restrict__ vts,
    const float* __restrict__ ap, const float* __restrict__ avw,
    __half* __restrict__ oh)
{
    extern __shared__ char sm[];
    __half* sQh = (__half*)(sm + A_OFF_Q);
    __half* sQl = sQh + 128 * QSTR;
    float* sAV = (float*)(sm + A_OFF_AV);

    const int tid  = threadIdx.x;
    const int wid  = tid >> 5;
    const int lane = tid & 31;
    const int gid  = lane >> 2;
    const int tq   = lane & 3;

    const int qt = (gridDim.x - 1) - blockIdx.x;
    const int bh = blockIdx.y;
    const int b  = bh >> 5;
    const int h  = bh & 31;
    const float scale = 0.08838834764831845f;

    const int wm = wid * 16;
    const size_t qgbase = ((size_t)(b * Ss) + qt * 128) * Dd + h * HDd;
    const size_t vgbase = (size_t)bh * HDd * Ss;

    for (int i = tid; i < 2048; i += 256) {
        const int r = i >> 4, c = i & 15;
        *(uint4*)(sQh + r * QSTR + c * 8) = *(const uint4*)(qhi + qgbase + (size_t)r * Dd + c * 8);
        *(uint4*)(sQl + r * QSTR + c * 8) = *(const uint4*)(qlo + qgbase + (size_t)r * Dd + c * 8);
    }
    for (int i = tid; i < ALl * HDd; i += 256) {
        const int l = i >> 7, d = i & 127;
        sAV[l * 132 + d] = avw[(size_t)l * Dd + h * HDd + d];
    }

    auto prefetch = [&](int kt_, int s) {
        __half* kh = (__half*)(sm + A_OFF_K + s * 17408);
        __half* vh = (__half*)(sm + A_OFF_V + s * 18432);
        const size_t kb = ((size_t)(b * Ss) + kt_ * 64) * Dd + h * HDd;
        const size_t vb = vgbase + (size_t)kt_ * 64;
        for (int i = tid; i < 1024; i += 256) {
            const int r = i >> 4, c = i & 15;
            cp16(kh + r * QSTR + c * 8, ks + kb + (size_t)r * Dd + c * 8);
        }
        for (int i = tid; i < 1024; i += 256) {
            const int d = i >> 3, c = i & 7;
            cp16(vh + d * VSTR + c * 8, vts + vb + (size_t)d * Ss + c * 8);
        }
        CP_COMMIT();
    };

    prefetch(0, 0);

    const int rq0 = qt * 128 + wm + gid;
    const int rq1 = rq0 + 8;

    float m0 = -1e30f, m1 = -1e30f, l0 = 0.0f, l1 = 0.0f;
    float o[16][4];
    #pragma unroll
    for (int nt = 0; nt < 16; nt++)
        #pragma unroll
        for (int j = 0; j < 4; j++) o[nt][j] = 0.0f;

    const int ktmax = 2 * qt + 1;
    for (int kt = 0; kt <= ktmax; kt++) {
        const int s = kt & 1;
        if (kt < ktmax) { prefetch(kt + 1, s ^ 1); CP_WAIT(1); }
        else            { CP_WAIT(0); }
        __syncthreads();

        const __half* kh = (const __half*)(sm + A_OFF_K + s * 17408);

        float sacc[8][4];
        #pragma unroll
        for (int nt = 0; nt < 8; nt++)
            #pragma unroll
            for (int j = 0; j < 4; j++) sacc[nt][j] = 0.0f;

        #pragma unroll
        for (int ksx = 0; ksx < 8; ksx++) {
            const int kb = ksx * 16 + tq * 2;
            const int ra = wm + gid;
            uint32_t ah[4], al[4];
            ah[0] = *(const uint32_t*)(sQh + ra * QSTR + kb);
            ah[1] = *(const uint32_t*)(sQh + (ra + 8) * QSTR + kb);
            ah[2] = *(const uint32_t*)(sQh + ra * QSTR + kb + 8);
            ah[3] = *(const uint32_t*)(sQh + (ra + 8) * QSTR + kb + 8);
            al[0] = *(const uint32_t*)(sQl + ra * QSTR + kb);
            al[1] = *(const uint32_t*)(sQl + (ra + 8) * QSTR + kb);
            al[2] = *(const uint32_t*)(sQl + ra * QSTR + kb + 8);
            al[3] = *(const uint32_t*)(sQl + (ra + 8) * QSTR + kb + 8);
            #pragma unroll
            for (int nt = 0; nt < 8; nt++) {
                const int n = nt * 8 + gid;
                uint32_t bf[2];
                bf[0] = *(const uint32_t*)(kh + n * QSTR + kb);
                bf[1] = *(const uint32_t*)(kh + n * QSTR + kb + 8);
                mma16816(sacc[nt], ah, bf);
                mma16816(sacc[nt], al, bf);
            }
        }

        const bool maybe = (kt >= 2 * qt);
        #pragma unroll
        for (int nt = 0; nt < 8; nt++) {
            const int c = kt * 64 + nt * 8 + tq * 2;
            sacc[nt][0] *= scale; sacc[nt][1] *= scale;
            sacc[nt][2] *= scale; sacc[nt][3] *= scale;
            if (maybe) {
                if (c     > rq0) sacc[nt][0] = -1e30f;
                if (c + 1 > rq0) sacc[nt][1] = -1e30f;
                if (c     > rq1) sacc[nt][2] = -1e30f;
                if (c + 1 > rq1) sacc[nt][3] = -1e30f;
            }
        }

        float mx0 = -1e30f, mx1 = -1e30f;
        #pragma unroll
        for (int nt = 0; nt < 8; nt++) {
            mx0 = fmaxf(mx0, fmaxf(sacc[nt][0], sacc[nt][1]));
            mx1 = fmaxf(mx1, fmaxf(sacc[nt][2], sacc[nt][3]));
        }
        mx0 = fmaxf(mx0, __shfl_xor_sync(0xFFFFFFFFu, mx0, 1));
        mx0 = fmaxf(mx0, __shfl_xor_sync(0xFFFFFFFFu, mx0, 2));
        mx1 = fmaxf(mx1, __shfl_xor_sync(0xFFFFFFFFu, mx1, 1));
        mx1 = fmaxf(mx1, __shfl_xor_sync(0xFFFFFFFFu, mx1, 2));
        const float mn0 = fmaxf(m0, mx0), mn1 = fmaxf(m1, mx1);
        const float a0 = __expf(m0 - mn0), a1 = __expf(m1 - mn1);
        m0 = mn0; m1 = mn1;

        float sum0 = 0.0f, sum1 = 0.0f;
        #pragma unroll
        for (int nt = 0; nt < 8; nt++) {
            sacc[nt][0] = __expf(sacc[nt][0] - m0);
            sacc[nt][1] = __expf(sacc[nt][1] - m0);
            sacc[nt][2] = __expf(sacc[nt][2] - m1);
            sacc[nt][3] = __expf(sacc[nt][3] - m1);
            sum0 += sacc[nt][0] + sacc[nt][1];
            sum1 += sacc[nt][2] + sacc[nt][3];
        }
        sum0 += __shfl_xor_sync(0xFFFFFFFFu, sum0, 1);
        sum0 += __shfl_xor_sync(0xFFFFFFFFu, sum0, 2);
        sum1 += __shfl_xor_sync(0xFFFFFFFFu, sum1, 1);
        sum1 += __shfl_xor_sync(0xFFFFFFFFu, sum1, 2);
        l0 = l0 * a0 + sum0;
        l1 = l1 * a1 + sum1;

        #pragma unroll
        for (int nt = 0; nt < 16; nt++) {
            o[nt][0] *= a0; o[nt][1] *= a0;
            o[nt][2] *= a1; o[nt][3] *= a1;
        }

        // P -> fp16 hi/lo A-fragments (exact 2-term)
        uint32_t pfh[4][4], pfl[4][4];
        #pragma unroll
        for (int kc = 0; kc < 4; kc++) {
            #pragma unroll
            for (int half_ = 0; half_ < 2; half_++) {
                const int nt = 2 * kc + half_;
                float p0 = sacc[nt][0], p1 = sacc[nt][1];
                float p2 = sacc[nt][2], p3 = sacc[nt][3];
                __half h0 = __float2half(p0), h1 = __float2half(p1);
                __half h2 = __float2half(p2), h3 = __float2half(p3);
                __half2 hv01 = __halves2half2(h0, h1), hv23 = __halves2half2(h2, h3);
                pfh[kc][half_ * 2]     = *(uint32_t*)&hv01;
                pfh[kc][half_ * 2 + 1] = *(uint32_t*)&hv23;
                __half2 lv01 = __halves2half2(__float2half(p0 - __half2float(h0)),
                                              __float2half(p1 - __half2float(h1)));
                __half2 lv23 = __halves2half2(__float2half(p2 - __half2float(h2)),
                                              __float2half(p3 - __half2float(h3)));
                pfl[kc][half_ * 2]     = *(uint32_t*)&lv01;
                pfl[kc][half_ * 2 + 1] = *(uint32_t*)&lv23;
            }
        }

        const __half* vh = (const __half*)(sm + A_OFF_V + s * 18432);
        #pragma unroll
        for (int kc = 0; kc < 4; kc++) {
            const int kb = kc * 16 + tq * 2;
            #pragma unroll
            for (int nt = 0; nt < 16; nt++) {
                const int n = nt * 8 + gid;
                uint32_t vf[2];
                vf[0] = *(const uint32_t*)(vh + n * VSTR + kb);
                vf[1] = *(const uint32_t*)(vh + n * VSTR + kb + 8);
                mma16816(o[nt], pfh[kc], vf);
                mma16816(o[nt], pfl[kc], vf);
            }
        }
        __syncthreads();
    }

    const float li0 = 1.0f / l0, li1 = 1.0f / l1;
    const float* ap0p = ap + ((size_t)bh * Ss + rq0) * 12;
    const float* ap1p = ap + ((size_t)bh * Ss + rq1) * 12;
    float ap0[ALl], ap1[ALl];
    #pragma unroll
    for (int l = 0; l < ALl; l++) { ap0[l] = ap0p[l]; ap1[l] = ap1p[l]; }

    const size_t ob0 = qgbase + (size_t)(wm + gid) * Dd;
    const size_t ob1 = ob0 + 8 * Dd;
    #pragma unroll
    for (int nt = 0; nt < 16; nt++) {
        const int c = nt * 8 + tq * 2;
        float v0 = o[nt][0] * li0, v1 = o[nt][1] * li0;
        float v2 = o[nt][2] * li1, v3 = o[nt][3] * li1;
        #pragma unroll
        for (int l = 0; l < ALl; l++) {
            const float av0 = sAV[l * 132 + c];
            const float av1 = sAV[l * 132 + c + 1];
            v0 = fmaf(ap0[l], av0, v0);
            v1 = fmaf(ap0[l], av1, v1);
            v2 = fmaf(ap1[l], av0, v2);
            v3 = fmaf(ap1[l], av1, v3);
        }
        *(__half2*)(oh + ob0 + c) = __halves2half2(__float2half(v0), __float2half(v1));
        *(__half2*)(oh + ob1 + c) = __halves2half2(__float2half(v2), __float2half(v3));
    }
}

// ---------------------------------------------------------------------------
// Launch
// Inputs: 0=x 1=cos 2=sin 3=mask(unused) 4=wq 5=wk 6=wv 7=wo 8=gate 9=adapter
// ---------------------------------------------------------------------------
extern "C" void kernel_launch(void* const* d_in, const int* in_sizes, int n_in,
                              void* d_out, int out_size)
{
    const float* x       = (const float*)d_in[0];
    const float* cosb    = (const float*)d_in[1];
    const float* sinb    = (const float*)d_in[2];
    const float* wq      = (const float*)d_in[4];
    const float* wk      = (const float*)d_in[5];
    const float* wv      = (const float*)d_in[6];
    const float* wo      = (const float*)d_in[7];
    const float* gate    = (const float*)d_in[8];
    const float* adapter = (const float*)d_in[9];
    float* out = (float*)d_out;

    float *xv, *akp, *avp, *app;
    cudaGetSymbolAddress((void**)&xv,  g_xv);
    cudaGetSymbolAddress((void**)&akp, g_ak);
    cudaGetSymbolAddress((void**)&avp, g_av);
    cudaGetSymbolAddress((void**)&app, g_ap);

    __half *xh, *qhi, *qlo, *ksb, *vtb;
    __half *wqh, *wkh, *wvh, *woh;
    cudaGetSymbolAddress((void**)&xh,  g_xh);
    cudaGetSymbolAddress((void**)&qhi, g_qhi);
    cudaGetSymbolAddress((void**)&qlo, g_qlo);
    cudaGetSymbolAddress((void**)&ksb, g_ks);
    cudaGetSymbolAddress((void**)&vtb, g_vts);
    cudaGetSymbolAddress((void**)&wqh, g_wq);
    cudaGetSymbolAddress((void**)&wkh, g_wk);
    cudaGetSymbolAddress((void**)&wvh, g_wv);
    cudaGetSymbolAddress((void**)&woh, g_wo);

    cudaFuncSetAttribute(gemm_hmma<0>, cudaFuncAttributeMaxDynamicSharedMemorySize, GSMEM);
    cudaFuncSetAttribute(gemm_hmma<1>, cudaFuncAttributeMaxDynamicSharedMemorySize, GSMEM);
    cudaFuncSetAttribute(gemm_hmma<2>, cudaFuncAttributeMaxDynamicSharedMemorySize, GSMEM);
    cudaFuncSetAttribute(attn_tc2, cudaFuncAttributeMaxDynamicSharedMemorySize, ATTN2_SMEM);

    // Weight transpose (fp16 single)
    dim3 tb(32, 8), tg(Dd / 32, Dd / 32);
    tsplit_kernel<<<tg, tb>>>(wq, wqh);
    tsplit_kernel<<<tg, tb>>>(wk, wkh);
    tsplit_kernel<<<tg, tb>>>(wv, wvh);
    tsplit_kernel<<<tg, tb>>>(wo, woh);

    // x -> fp16 single
    tofp16_kernel<<<(Mrows * Dd / 4) / 256, 256>>>(x, xh);

    // Projections (single-A): Q (rope, hi/lo out), K (rope, single out), V (fp32)
    dim3 gg(Dd / 128, Mrows / 128);   // (32, 32)
    gemm_hmma<1><<<gg, 256, GSMEM>>>(xh, wqh, nullptr, qhi, qlo, cosb, sinb);
    gemm_hmma<2><<<gg, 256, GSMEM>>>(xh, wkh, nullptr, ksb, nullptr, cosb, sinb);
    gemm_hmma<0><<<gg, 256, GSMEM>>>(xh, wvh, xv, nullptr, nullptr, nullptr, nullptr);

    vtsplit_kernel<<<dim3(Ss / 32, HDd / 32, Bb * Hh), tb>>>(xv, vtb);

    adapter_gemm<<<Dd / 256, 256>>>(adapter, wk, akp);
    adapter_gemm<<<Dd / 256, 256>>>(adapter, wv, avp);
    adapter_probs<<<dim3(Ss / 128, Bb * Hh), 128>>>(qhi, qlo, akp, gate, app);

    // FA2 tensor-core attention -> O fp16 single (reuse xh buffer)
    attn_tc2<<<dim3(Ss / 128, Bb * Hh), 256, ATTN2_SMEM>>>(
        qhi, qlo, ksb, vtb, app, avp, xh);

    // Output projection (single-A)
    gemm_hmma<0><<<gg, 256, GSMEM>>>(xh, woh, out, nullptr, nullptr, nullptr, nullptr);
}

// round 17
// speedup vs baseline: 1.3665x; 1.0322x over previous
#include <cuda_runtime.h>
#include <cuda_fp16.h>
#include <cstdint>

// Problem constants
#define Bb   2
#define Ss   2048
#define Dd   4096
#define Hh   32
#define HDd  128
#define ALl  10
#define Mrows (Bb * Ss)   // 4096

__device__ __forceinline__ uint32_t smem_u32(const void* p) {
    uint32_t a;
    asm("{ .reg .u64 t; cvta.to.shared.u64 t, %1; cvt.u32.u64 %0, t; }" : "=r"(a) : "l"(p));
    return a;
}
__device__ __forceinline__ void cp16(void* smem_dst, const void* gsrc) {
    uint32_t s = smem_u32(smem_dst);
    asm volatile("cp.async.cg.shared.global [%0], [%1], 16;" :: "r"(s), "l"(gsrc));
}
#define CP_COMMIT() asm volatile("cp.async.commit_group;" ::: "memory")
#define CP_WAIT(n)  asm volatile("cp.async.wait_group %0;" :: "n"(n) : "memory")

// fp16 m16n8k16 mma, fp32 accum
__device__ __forceinline__ void mma16816(float* c, const uint32_t* a, const uint32_t* b) {
    asm volatile(
        "mma.sync.aligned.m16n8k16.row.col.f32.f16.f16.f32 "
        "{%0,%1,%2,%3}, {%4,%5,%6,%7}, {%8,%9}, {%0,%1,%2,%3};"
        : "+f"(c[0]), "+f"(c[1]), "+f"(c[2]), "+f"(c[3])
        : "r"(a[0]), "r"(a[1]), "r"(a[2]), "r"(a[3]), "r"(b[0]), "r"(b[1]));
}

// ---------------------------------------------------------------------------
// Scratch buffers
// ---------------------------------------------------------------------------
__device__ float g_xv[Mrows * Dd];
__device__ float g_ak[ALl * Dd];
__device__ float g_av[ALl * Dd];
__device__ float g_ap[(size_t)Bb * Hh * Ss * 12];   // gated adapter probs

__device__ __half g_xh [Mrows * Dd];   // x fp16 single; later O fp16 single
__device__ __half g_qs [Mrows * Dd];   // Q post-rope single
__device__ __half g_ks [Mrows * Dd];   // K post-rope single
__device__ __half g_vts[Mrows * Dd];   // V^T per head [b,h,d,s] single
// transposed weights, single fp16: Wt[n][k] = W[k][n]
__device__ __half g_wq[Dd * Dd];
__device__ __half g_wk[Dd * Dd];
__device__ __half g_wv[Dd * Dd];
__device__ __half g_wo[Dd * Dd];

// ---------------------------------------------------------------------------
// Convert fp32 -> fp16 single
// ---------------------------------------------------------------------------
__global__ __launch_bounds__(256) void tofp16_kernel(
    const float* __restrict__ A, __half* __restrict__ o)
{
    const int i = blockIdx.x * 256 + threadIdx.x;
    float4 v = ((const float4*)A)[i];
    ((__half2*)o)[2 * i]     = __halves2half2(__float2half(v.x), __float2half(v.y));
    ((__half2*)o)[2 * i + 1] = __halves2half2(__float2half(v.z), __float2half(v.w));
}

// ---------------------------------------------------------------------------
// Transpose: W[K,N] fp32 -> Wt[N,K] fp16 single
// ---------------------------------------------------------------------------
__global__ __launch_bounds__(256) void tsplit_kernel(
    const float* __restrict__ W, __half* __restrict__ o)
{
    __shared__ float t[32][33];
    const int tx = threadIdx.x, ty = threadIdx.y;
    const int x = blockIdx.x * 32 + tx;
    const int y0 = blockIdx.y * 32;
    #pragma unroll
    for (int j = ty; j < 32; j += 8)
        t[j][tx] = W[(size_t)(y0 + j) * Dd + x];
    __syncthreads();
    const int ox = blockIdx.y * 32 + tx;
    const int oy0 = blockIdx.x * 32;
    #pragma unroll
    for (int j = ty; j < 32; j += 8)
        o[(size_t)(oy0 + j) * Dd + ox] = __float2half(t[tx][j]);
}

// ---------------------------------------------------------------------------
// V transpose per head: xv fp32 [(b,s),(h,d)] -> vt fp16 [(b,h,d),(s)]
// ---------------------------------------------------------------------------
__global__ __launch_bounds__(256) void vtsplit_kernel(
    const float* __restrict__ V, __half* __restrict__ o)
{
    __shared__ float t[32][33];
    const int tx = threadIdx.x, ty = threadIdx.y;
    const int bh = blockIdx.z;
    const int b = bh >> 5, h = bh & 31;
    const int s0 = blockIdx.x * 32;
    const int d0 = blockIdx.y * 32;
    #pragma unroll
    for (int j = ty; j < 32; j += 8)
        t[j][tx] = V[(size_t)(b * Ss + s0 + j) * Dd + h * HDd + d0 + tx];
    __syncthreads();
    #pragma unroll
    for (int j = ty; j < 32; j += 8)
        o[((size_t)bh * HDd + d0 + j) * Ss + s0 + tx] = __float2half(t[tx][j]);
}

// ---------------------------------------------------------------------------
// HMMA GEMM: 128x128 tile, BK=32, single fp16 A and B,
// 4-stage cp.async pipeline with XOR chunk swizzle, 2 CTAs/SM.
// MODE 0: fp32 C. MODE 2: RoPE + fp16 single C (Q and K).
// ---------------------------------------------------------------------------
#define TILEB  8192                   // 128 rows x 64 B
#define STAGEB (2 * TILEB)            // A, B = 16384 B
#define GSMEM  (4 * STAGEB)           // 65536 B -> 2 CTAs/SM

template<int MODE>
__global__ __launch_bounds__(256, 2) void gemm_hmma(
    const __half* __restrict__ A, const __half* __restrict__ B,
    float* __restrict__ C, __half* __restrict__ Ch,
    const float* __restrict__ cosb, const float* __restrict__ sinb)
{
    extern __shared__ char smem[];
    const int tid  = threadIdx.x;
    const int wid  = tid >> 5;
    const int lane = tid & 31;
    const int gid  = lane >> 2;
    const int tq   = lane & 3;

    const int warp_m = (wid & 3) * 32;
    const int warp_n = (wid >> 2) * 64;
    const size_t arow0 = (size_t)blockIdx.y * 128;
    const size_t brow0 = (size_t)blockIdx.x * 128;

    const uint32_t swv = (uint32_t)((gid & 6) >> 1);
    uint32_t co[4];
    #pragma unroll
    for (int c = 0; c < 4; c++) co[c] = ((uint32_t)c ^ swv) << 4;
    const uint32_t tqb = (uint32_t)(tq * 4);

    float acc[2][8][4];
    #pragma unroll
    for (int mt = 0; mt < 2; mt++)
        #pragma unroll
        for (int nt = 0; nt < 8; nt++)
            #pragma unroll
            for (int j = 0; j < 4; j++) acc[mt][nt][j] = 0.0f;

    auto load_stage = [&](int s, int k0) {
        char* stg = smem + s * STAGEB;
        #pragma unroll
        for (int i = tid; i < 512; i += 256) {
            const int r = i >> 2, kc = i & 3;
            const int kcs = kc ^ ((r & 6) >> 1);
            const size_t ga = (arow0 + r) * (size_t)Dd + k0 + kc * 8;
            const size_t gb = (brow0 + r) * (size_t)Dd + k0 + kc * 8;
            char* dst = stg + r * 64 + kcs * 16;
            cp16(dst,         A + ga);
            cp16(dst + TILEB, B + gb);
        }
        CP_COMMIT();
    };

    const int NCH = Dd / 32;   // 128
    load_stage(0, 0);
    load_stage(1, 32);
    load_stage(2, 64);
    CP_WAIT(2);
    __syncthreads();

    for (int ch = 0; ch < NCH; ch++) {
        if (ch + 3 < NCH) load_stage((ch + 3) & 3, (ch + 3) * 32);

        const char* stg = smem + (ch & 3) * STAGEB;
        const char* sA = stg;
        const char* sB = stg + TILEB;

        #pragma unroll
        for (int ks = 0; ks < 2; ks++) {
            const uint32_t c0 = co[ks * 2], c1 = co[ks * 2 + 1];
            uint32_t af[2][4];
            #pragma unroll
            for (int mt = 0; mt < 2; mt++) {
                const uint32_t r0b = (uint32_t)((warp_m + mt * 16 + gid) * 64) + tqb;
                const uint32_t r1b = r0b + 8 * 64;
                af[mt][0] = *(const uint32_t*)(sA + r0b + c0);
                af[mt][1] = *(const uint32_t*)(sA + r1b + c0);
                af[mt][2] = *(const uint32_t*)(sA + r0b + c1);
                af[mt][3] = *(const uint32_t*)(sA + r1b + c1);
            }
            #pragma unroll
            for (int nt = 0; nt < 8; nt++) {
                const uint32_t nb = (uint32_t)((warp_n + nt * 8 + gid) * 64) + tqb;
                uint32_t bf[2];
                bf[0] = *(const uint32_t*)(sB + nb + c0);
                bf[1] = *(const uint32_t*)(sB + nb + c1);
                #pragma unroll
                for (int mt = 0; mt < 2; mt++)
                    mma16816(acc[mt][nt], af[mt], bf);
            }
        }

        if (ch < NCH - 3)       CP_WAIT(2);
        else if (ch == NCH - 3) CP_WAIT(1);
        else                    CP_WAIT(0);
        __syncthreads();
    }

    #pragma unroll
    for (int mt = 0; mt < 2; mt++) {
        const size_t r0 = arow0 + warp_m + mt * 16 + gid;
        #pragma unroll
        for (int nt = 0; nt < 8; nt++) {
            const size_t c = brow0 + warp_n + nt * 8 + tq * 2;
            if (MODE == 0) {
                *(float2*)(C + r0 * Dd + c)       = make_float2(acc[mt][nt][0], acc[mt][nt][1]);
                *(float2*)(C + (r0 + 8) * Dd + c) = make_float2(acc[mt][nt][2], acc[mt][nt][3]);
            } else {
                const int j = ((int)c & 127) >> 1;
                #pragma unroll
                for (int rr = 0; rr < 2; rr++) {
                    const size_t r = r0 + rr * 8;
                    const int sidx = (int)(r & (Ss - 1));
                    const float cs = cosb[sidx * 64 + j];
                    const float sn = sinb[sidx * 64 + j];
                    const float x0 = acc[mt][nt][rr * 2], x1 = acc[mt][nt][rr * 2 + 1];
                    const float o0 = x0 * cs - x1 * sn;
                    const float o1 = x0 * sn + x1 * cs;
                    *(__half2*)(Ch + r * Dd + c) =
                        __halves2half2(__float2half(o0), __float2half(o1));
                }
            }
        }
    }
}

// ---------------------------------------------------------------------------
// Adapter GEMM: C[AL, D] = A[AL, D] @ W[D, D]  (tiny M=10, fp32)
// ---------------------------------------------------------------------------
__global__ __launch_bounds__(256) void adapter_gemm(
    const float* __restrict__ A, const float* __restrict__ W,
    float* __restrict__ C)
{
    __shared__ float sA[ALl][256];
    const int n = blockIdx.x * 256 + threadIdx.x;

    float acc[ALl];
    #pragma unroll
    for (int l = 0; l < ALl; l++) acc[l] = 0.0f;

    for (int k0 = 0; k0 < Dd; k0 += 256) {
        for (int i = threadIdx.x; i < ALl * 256; i += 256)
            sA[i >> 8][i & 255] = A[(size_t)(i >> 8) * Dd + k0 + (i & 255)];
        __syncthreads();
        for (int kk = 0; kk < 256; kk++) {
            float w = W[(size_t)(k0 + kk) * Dd + n];
            #pragma unroll
            for (int l = 0; l < ALl; l++)
                acc[l] = fmaf(sA[l][kk], w, acc[l]);
        }
        __syncthreads();
    }
    #pragma unroll
    for (int l = 0; l < ALl; l++) C[(size_t)l * Dd + n] = acc[l];
}

// ---------------------------------------------------------------------------
// Adapter probs: ap[bh][s][l] = gate[h] * softmax_l(Q[s,h,:]·AK[l,h,:]*scale)
// ---------------------------------------------------------------------------
__global__ __launch_bounds__(128) void adapter_probs(
    const __half* __restrict__ qs,
    const float* __restrict__ akw, const float* __restrict__ gate,
    float* __restrict__ ap)
{
    __shared__ float sak[ALl][128];
    const int tid = threadIdx.x;
    const int bh = blockIdx.y;
    const int b = bh >> 5, h = bh & 31;
    const int s = blockIdx.x * 128 + tid;
    const float scale = 0.08838834764831845f;

    for (int i = tid; i < ALl * 128; i += 128)
        sak[i >> 7][i & 127] = akw[(size_t)(i >> 7) * Dd + h * HDd + (i & 127)];
    __syncthreads();

    const size_t qb = (size_t)(b * Ss + s) * Dd + h * HDd;
    float acc[ALl];
    #pragma unroll
    for (int l = 0; l < ALl; l++) acc[l] = 0.0f;
    #pragma unroll 4
    for (int c = 0; c < 16; c++) {
        uint4 vh = *(const uint4*)(qs + qb + c * 8);
        const __half2* ph = (const __half2*)&vh;
        #pragma unroll
        for (int u = 0; u < 4; u++) {
            float q0 = __low2float(ph[u]);
            float q1 = __high2float(ph[u]);
            const int d = c * 8 + u * 2;
            #pragma unroll
            for (int l = 0; l < ALl; l++)
                acc[l] = fmaf(q0, sak[l][d], fmaf(q1, sak[l][d + 1], acc[l]));
        }
    }
    float amax = -1e30f;
    #pragma unroll
    for (int l = 0; l < ALl; l++) { acc[l] *= scale; amax = fmaxf(amax, acc[l]); }
    float asum = 0.0f;
    #pragma unroll
    for (int l = 0; l < ALl; l++) { acc[l] = __expf(acc[l] - amax); asum += acc[l]; }
    const float g = gate[h] / asum;
    float* dst = ap + ((size_t)bh * Ss + s) * 12;
    #pragma unroll
    for (int l = 0; l < ALl; l++) dst[l] = acc[l] * g;
}

// ---------------------------------------------------------------------------
// FA2-style tensor-core attention, single fp16 operands throughout.
// 128 queries/CTA, 8 warps x 16 rows, K tiles of 64, double-buffered.
// O written single fp16 (A-operand of Wo only).
// ---------------------------------------------------------------------------
#define QSTR 136
#define VSTR 72
#define A_OFF_Q  0                       // Q single 34816
#define A_OFF_K  34816                   // K single stage 17408 x2
#define A_OFF_V  69632                   // V single stage 18432 x2
#define A_OFF_AV 106496                  // fp32 10x132 = 5280
#define ATTN2_SMEM 111776

__global__ __launch_bounds__(256, 1) void attn_tc2(
    const __half* __restrict__ qs,  const __half* __restrict__ ks,
    const __half* __restrict__ vts,
    const float* __restrict__ ap, const float* __restrict__ avw,
    __half* __restrict__ oh)
{
    extern __shared__ char sm[];
    __half* sQ = (__half*)(sm + A_OFF_Q);
    float* sAV = (float*)(sm + A_OFF_AV);

    const int tid  = threadIdx.x;
    const int wid  = tid >> 5;
    const int lane = tid & 31;
    const int gid  = lane >> 2;
    const int tq   = lane & 3;

    const int qt = (gridDim.x - 1) - blockIdx.x;
    const int bh = blockIdx.y;
    const int b  = bh >> 5;
    const int h  = bh & 31;
    const float scale = 0.08838834764831845f;

    const int wm = wid * 16;
    const size_t qgbase = ((size_t)(b * Ss) + qt * 128) * Dd + h * HDd;
    const size_t vgbase = (size_t)bh * HDd * Ss;

    for (int i = tid; i < 2048; i += 256) {
        const int r = i >> 4, c = i & 15;
        *(uint4*)(sQ + r * QSTR + c * 8) = *(const uint4*)(qs + qgbase + (size_t)r * Dd + c * 8);
    }
    for (int i = tid; i < ALl * HDd; i += 256) {
        const int l = i >> 7, d = i & 127;
        sAV[l * 132 + d] = avw[(size_t)l * Dd + h * HDd + d];
    }

    auto prefetch = [&](int kt_, int s) {
        __half* kh = (__half*)(sm + A_OFF_K + s * 17408);
        __half* vh = (__half*)(sm + A_OFF_V + s * 18432);
        const size_t kb = ((size_t)(b * Ss) + kt_ * 64) * Dd + h * HDd;
        const size_t vb = vgbase + (size_t)kt_ * 64;
        for (int i = tid; i < 1024; i += 256) {
            const int r = i >> 4, c = i & 15;
            cp16(kh + r * QSTR + c * 8, ks + kb + (size_t)r * Dd + c * 8);
        }
        for (int i = tid; i < 1024; i += 256) {
            const int d = i >> 3, c = i & 7;
            cp16(vh + d * VSTR + c * 8, vts + vb + (size_t)d * Ss + c * 8);
        }
        CP_COMMIT();
    };

    prefetch(0, 0);

    const int rq0 = qt * 128 + wm + gid;
    const int rq1 = rq0 + 8;

    float m0 = -1e30f, m1 = -1e30f, l0 = 0.0f, l1 = 0.0f;
    float o[16][4];
    #pragma unroll
    for (int nt = 0; nt < 16; nt++)
        #pragma unroll
        for (int j = 0; j < 4; j++) o[nt][j] = 0.0f;

    const int ktmax = 2 * qt + 1;
    for (int kt = 0; kt <= ktmax; kt++) {
        const int s = kt & 1;
        if (kt < ktmax) { prefetch(kt + 1, s ^ 1); CP_WAIT(1); }
        else            { CP_WAIT(0); }
        __syncthreads();

        const __half* kh = (const __half*)(sm + A_OFF_K + s * 17408);

        float sacc[8][4];
        #pragma unroll
        for (int nt = 0; nt < 8; nt++)
            #pragma unroll
            for (int j = 0; j < 4; j++) sacc[nt][j] = 0.0f;

        #pragma unroll
        for (int ksx = 0; ksx < 8; ksx++) {
            const int kb = ksx * 16 + tq * 2;
            const int ra = wm + gid;
            uint32_t af[4];
            af[0] = *(const uint32_t*)(sQ + ra * QSTR + kb);
            af[1] = *(const uint32_t*)(sQ + (ra + 8) * QSTR + kb);
            af[2] = *(const uint32_t*)(sQ + ra * QSTR + kb + 8);
            af[3] = *(const uint32_t*)(sQ + (ra + 8) * QSTR + kb + 8);
            #pragma unroll
            for (int nt = 0; nt < 8; nt++) {
                const int n = nt * 8 + gid;
                uint32_t bf[2];
                bf[0] = *(const uint32_t*)(kh + n * QSTR + kb);
                bf[1] = *(const uint32_t*)(kh + n * QSTR + kb + 8);
                mma16816(sacc[nt], af, bf);
            }
        }

        const bool maybe = (kt >= 2 * qt);
        #pragma unroll
        for (int nt = 0; nt < 8; nt++) {
            const int c = kt * 64 + nt * 8 + tq * 2;
            sacc[nt][0] *= scale; sacc[nt][1] *= scale;
            sacc[nt][2] *= scale; sacc[nt][3] *= scale;
            if (maybe) {
                if (c     > rq0) sacc[nt][0] = -1e30f;
                if (c + 1 > rq0) sacc[nt][1] = -1e30f;
                if (c     > rq1) sacc[nt][2] = -1e30f;
                if (c + 1 > rq1) sacc[nt][3] = -1e30f;
            }
        }

        float mx0 = -1e30f, mx1 = -1e30f;
        #pragma unroll
        for (int nt = 0; nt < 8; nt++) {
            mx0 = fmaxf(mx0, fmaxf(sacc[nt][0], sacc[nt][1]));
            mx1 = fmaxf(mx1, fmaxf(sacc[nt][2], sacc[nt][3]));
        }
        mx0 = fmaxf(mx0, __shfl_xor_sync(0xFFFFFFFFu, mx0, 1));
        mx0 = fmaxf(mx0, __shfl_xor_sync(0xFFFFFFFFu, mx0, 2));
        mx1 = fmaxf(mx1, __shfl_xor_sync(0xFFFFFFFFu, mx1, 1));
        mx1 = fmaxf(mx1, __shfl_xor_sync(0xFFFFFFFFu, mx1, 2));
        const float mn0 = fmaxf(m0, mx0), mn1 = fmaxf(m1, mx1);
        const float a0 = __expf(m0 - mn0), a1 = __expf(m1 - mn1);
        m0 = mn0; m1 = mn1;

        float sum0 = 0.0f, sum1 = 0.0f;
        #pragma unroll
        for (int nt = 0; nt < 8; nt++) {
            sacc[nt][0] = __expf(sacc[nt][0] - m0);
            sacc[nt][1] = __expf(sacc[nt][1] - m0);
            sacc[nt][2] = __expf(sacc[nt][2] - m1);
            sacc[nt][3] = __expf(sacc[nt][3] - m1);
            sum0 += sacc[nt][0] + sacc[nt][1];
            sum1 += sacc[nt][2] + sacc[nt][3];
        }
        sum0 += __shfl_xor_sync(0xFFFFFFFFu, sum0, 1);
        sum0 += __shfl_xor_sync(0xFFFFFFFFu, sum0, 2);
        sum1 += __shfl_xor_sync(0xFFFFFFFFu, sum1, 1);
        sum1 += __shfl_xor_sync(0xFFFFFFFFu, sum1, 2);
        l0 = l0 * a0 + sum0;
        l1 = l1 * a1 + sum1;

        #pragma unroll
        for (int nt = 0; nt < 16; nt++) {
            o[nt][0] *= a0; o[nt][1] *= a0;
            o[nt][2] *= a1; o[nt][3] *= a1;
        }

        // P -> fp16 single A-fragments
        uint32_t pf[4][4];
        #pragma unroll
        for (int kc = 0; kc < 4; kc++) {
            #pragma unroll
            for (int half_ = 0; half_ < 2; half_++) {
                const int nt = 2 * kc + half_;
                __half2 hv01 = __halves2half2(__float2half(sacc[nt][0]),
                                              __float2half(sacc[nt][1]));
                __half2 hv23 = __halves2half2(__float2half(sacc[nt][2]),
                                              __float2half(sacc[nt][3]));
                pf[kc][half_ * 2]     = *(uint32_t*)&hv01;
                pf[kc][half_ * 2 + 1] = *(uint32_t*)&hv23;
            }
        }

        const __half* vh = (const __half*)(sm + A_OFF_V + s * 18432);
        #pragma unroll
        for (int kc = 0; kc < 4; kc++) {
            const int kb = kc * 16 + tq * 2;
            #pragma unroll
            for (int nt = 0; nt < 16; nt++) {
                const int n = nt * 8 + gid;
                uint32_t vf[2];
                vf[0] = *(const uint32_t*)(vh + n * VSTR + kb);
                vf[1] = *(const uint32_t*)(vh + n * VSTR + kb + 8);
                mma16816(o[nt], pf[kc], vf);
            }
        }
        __syncthreads();
    }

    const float li0 = 1.0f / l0, li1 = 1.0f / l1;
    const float* ap0p = ap + ((size_t)bh * Ss + rq0) * 12;
    const float* ap1p = ap + ((size_t)bh * Ss + rq1) * 12;
    float ap0[ALl], ap1[ALl];
    #pragma unroll
    for (int l = 0; l < ALl; l++) { ap0[l] = ap0p[l]; ap1[l] = ap1p[l]; }

    const size_t ob0 = qgbase + (size_t)(wm + gid) * Dd;
    const size_t ob1 = ob0 + 8 * Dd;
    #pragma unroll
    for (int nt = 0; nt < 16; nt++) {
        const int c = nt * 8 + tq * 2;
        float v0 = o[nt][0] * li0, v1 = o[nt][1] * li0;
        float v2 = o[nt][2] * li1, v3 = o[nt][3] * li1;
        #pragma unroll
        for (int l = 0; l < ALl; l++) {
            const float av0 = sAV[l * 132 + c];
            const float av1 = sAV[l * 132 + c + 1];
            v0 = fmaf(ap0[l], av0, v0);
            v1 = fmaf(ap0[l], av1, v1);
            v2 = fmaf(ap1[l], av0, v2);
            v3 = fmaf(ap1[l], av1, v3);
        }
        *(__half2*)(oh + ob0 + c) = __halves2half2(__float2half(v0), __float2half(v1));
        *(__half2*)(oh + ob1 + c) = __halves2half2(__float2half(v2), __float2half(v3));
    }
}

// ---------------------------------------------------------------------------
// Launch
// Inputs: 0=x 1=cos 2=sin 3=mask(unused) 4=wq 5=wk 6=wv 7=wo 8=gate 9=adapter
// ---------------------------------------------------------------------------
extern "C" void kernel_launch(void* const* d_in, const int* in_sizes, int n_in,
                              void* d_out, int out_size)
{
    const float* x       = (const float*)d_in[0];
    const float* cosb    = (const float*)d_in[1];
    const float* sinb    = (const float*)d_in[2];
    const float* wq      = (const float*)d_in[4];
    const float* wk      = (const float*)d_in[5];
    const float* wv      = (const float*)d_in[6];
    const float* wo      = (const float*)d_in[7];
    const float* gate    = (const float*)d_in[8];
    const float* adapter = (const float*)d_in[9];
    float* out = (float*)d_out;

    float *xv, *akp, *avp, *app;
    cudaGetSymbolAddress((void**)&xv,  g_xv);
    cudaGetSymbolAddress((void**)&akp, g_ak);
    cudaGetSymbolAddress((void**)&avp, g_av);
    cudaGetSymbolAddress((void**)&app, g_ap);

    __half *xh, *qsb, *ksb, *vtb;
    __half *wqh, *wkh, *wvh, *woh;
    cudaGetSymbolAddress((void**)&xh,  g_xh);
    cudaGetSymbolAddress((void**)&qsb, g_qs);
    cudaGetSymbolAddress((void**)&ksb, g_ks);
    cudaGetSymbolAddress((void**)&vtb, g_vts);
    cudaGetSymbolAddress((void**)&wqh, g_wq);
    cudaGetSymbolAddress((void**)&wkh, g_wk);
    cudaGetSymbolAddress((void**)&wvh, g_wv);
    cudaGetSymbolAddress((void**)&woh, g_wo);

    cudaFuncSetAttribute(gemm_hmma<0>, cudaFuncAttributeMaxDynamicSharedMemorySize, GSMEM);
    cudaFuncSetAttribute(gemm_hmma<2>, cudaFuncAttributeMaxDynamicSharedMemorySize, GSMEM);
    cudaFuncSetAttribute(attn_tc2, cudaFuncAttributeMaxDynamicSharedMemorySize, ATTN2_SMEM);

    // Weight transpose (fp16 single)
    dim3 tb(32, 8), tg(Dd / 32, Dd / 32);
    tsplit_kernel<<<tg, tb>>>(wq, wqh);
    tsplit_kernel<<<tg, tb>>>(wk, wkh);
    tsplit_kernel<<<tg, tb>>>(wv, wvh);
    tsplit_kernel<<<tg, tb>>>(wo, woh);

    // x -> fp16 single
    tofp16_kernel<<<(Mrows * Dd / 4) / 256, 256>>>(x, xh);

    // Projections (single-A): Q/K (rope, single out), V (fp32)
    dim3 gg(Dd / 128, Mrows / 128);   // (32, 32)
    gemm_hmma<2><<<gg, 256, GSMEM>>>(xh, wqh, nullptr, qsb, cosb, sinb);
    gemm_hmma<2><<<gg, 256, GSMEM>>>(xh, wkh, nullptr, ksb, cosb, sinb);
    gemm_hmma<0><<<gg, 256, GSMEM>>>(xh, wvh, xv, nullptr, nullptr, nullptr);

    vtsplit_kernel<<<dim3(Ss / 32, HDd / 32, Bb * Hh), tb>>>(xv, vtb);

    adapter_gemm<<<Dd / 256, 256>>>(adapter, wk, akp);
    adapter_gemm<<<Dd / 256, 256>>>(adapter, wv, avp);
    adapter_probs<<<dim3(Ss / 128, Bb * Hh), 128>>>(qsb, akp, gate, app);

    // FA2 tensor-core attention -> O fp16 single (reuse xh buffer)
    attn_tc2<<<dim3(Ss / 128, Bb * Hh), 256, ATTN2_SMEM>>>(
        qsb, ksb, vtb, app, avp, xh);

    // Output projection (single-A)
    gemm_hmma<0><<<gg, 256, GSMEM>>>(xh, woh, out, nullptr, nullptr, nullptr);
}